// round 8
// baseline (speedup 1.0000x reference)
#include <cuda_runtime.h>
#include <cuda_bf16.h>
#include <math.h>

// ---------------------------------------------------------------------------
// VQ-VAE vector quantizer, GB300 sm_103a
//   N=65536 tokens, D=256, K=1024 codes, fp32
//
// Reference-rounding-faithful distance:
//   dist_k = fp32( fp32(xnorm + cnorm_k) - 2*dot_k )
//   dot_k  = sequential fp32 FMA chain over d = 0..255 ascending
//   argmin = lowest index on exactly-equal rounded distances
//
// GEMM v4: token-pair-packed FFMA2 accumulators (zero broadcast MOVs),
// B stored pre-duplicated in smem, A+B streamed in 32-d double-buffered
// stages with half-stage software pipelining, 2 CTAs/SM (16 warps/SM).
// K split into quarters x 2 chunks; 8 per-segment results merged in
// assign_kernel with the same rounded-compare + lowest-index-tie predicate.
// ---------------------------------------------------------------------------

#define NTOK 65536
#define DIM  256
#define KCB  1024

#define OFF_LOSS   16777216
#define OFF_IDX    16777217
#define OFF_PERP   16842753
#define OFF_NCS    16842754
#define OFF_EMAW   16843778
#define OFF_W      17105922

// scratch (device globals -- no allocation allowed)
__device__ float  g_cnorm[KCB];
__device__ float  g_xnorm[NTOK];
__device__ float  g_counts[KCB];
__device__ float  g_dw[KCB * DIM];
__device__ double g_loss;
__device__ float  g_newcs[KCB];
__device__ float  g_hdist[8 * NTOK];   // per-(quarter,chunk) best rounded dist
__device__ int    g_hidx[8 * NTOK];    // per-(quarter,chunk) best global index

// ---------------------------------------------------------------------------
// packed f32x2 FMA (Blackwell FFMA2 -- only reachable via PTX). Each lane is
// an independent IEEE RNE fp32 FMA -> bit-identical to scalar fmaf chains.
// ---------------------------------------------------------------------------
__device__ __forceinline__ unsigned long long fma_f32x2(unsigned long long a,
                                                        unsigned long long b,
                                                        unsigned long long c) {
    unsigned long long d;
    asm("fma.rn.f32x2 %0, %1, %2, %3;" : "=l"(d) : "l"(a), "l"(b), "l"(c));
    return d;
}
__device__ __forceinline__ float2 unpack_f32x2(unsigned long long v) {
    float2 r;
    asm("mov.b64 {%0, %1}, %2;" : "=f"(r.x), "=f"(r.y) : "l"(v));
    return r;
}

// ---------------------------------------------------------------------------
// 0) zero scratch
// ---------------------------------------------------------------------------
__global__ void zero_kernel() {
    int i = blockIdx.x * blockDim.x + threadIdx.x;
    int stride = gridDim.x * blockDim.x;
    for (int j = i; j < KCB * DIM; j += stride) g_dw[j] = 0.0f;
    if (i < KCB) g_counts[i] = 0.0f;
    if (i == 0)  g_loss = 0.0;
}

// ---------------------------------------------------------------------------
// 1) row squared-norms: one warp per row. (xnorm ulp jitter shifts a token's
//    whole distance row by the same lattice amount: order/tie preserving.)
// ---------------------------------------------------------------------------
__global__ void rownorm_kernel(const float* __restrict__ M,
                               float* __restrict__ out, int nrows) {
    int w    = (blockIdx.x * blockDim.x + threadIdx.x) >> 5;
    int lane = threadIdx.x & 31;
    if (w >= nrows) return;
    const float4* row = (const float4*)(M + (size_t)w * DIM);
    float s = 0.0f;
    float4 v = row[lane];
    s += v.x * v.x + v.y * v.y + v.z * v.z + v.w * v.w;
    v = row[32 + lane];
    s += v.x * v.x + v.y * v.y + v.z * v.z + v.w * v.w;
#pragma unroll
    for (int off = 16; off >= 1; off >>= 1)
        s += __shfl_xor_sync(0xffffffffu, s, off);
    if (lane == 0) out[w] = s;
}

// ---------------------------------------------------------------------------
// 2) fused GEMM + reference-rounded argmin
//    block = 128 tokens x 256 codes (quarter of K), 256 threads.
//    thread tile = 8 tokens (4 packed pairs) x 8 codes per 128-code chunk.
//    smem/CTA: As[2][32][128] 32KB + BsD[2][32][256](dup) 64KB + cn + xn.
// ---------------------------------------------------------------------------
#define SM_B   8192          // float offset of BsD
#define SM_CN  24576
#define SM_XN  24832
#define SMEM_BYTES (24960 * 4)

// Transposed A tile store: token tok, local d -> swizzled [d][tok].
// Row = 128 floats = 32 granules(16B); granule g=tok>>2, low3 ^= (d>>2).
__device__ __forceinline__ void stage_A(float* __restrict__ dst,
                                        const float4* pv, int sr, int sc) {
#pragma unroll
    for (int i = 0; i < 4; i++) {
        int tok = sr + 32 * i;
        int g   = tok >> 2;
        float v[4] = {pv[i].x, pv[i].y, pv[i].z, pv[i].w};
#pragma unroll
        for (int j = 0; j < 4; j++) {
            int d   = sc + j;
            int gsw = (g & 24) | ((g ^ (d >> 2)) & 7);
            dst[d * 128 + gsw * 4 + (tok & 3)] = v[j];
        }
    }
}

// Duplicated B tile store: code c (0..127), local d.
// Row = 256 floats = 64 granules. Code c lives at granule (c>>5)*16+(c&15),
// dup-pair slot ((c>>4)&1)*2; granule low3 ^= (d>>2).
__device__ __forceinline__ void stage_B(float* __restrict__ dst,
                                        const float4* pv, int sr, int sc) {
#pragma unroll
    for (int i = 0; i < 4; i++) {
        int c    = sr + 32 * i;
        int g    = ((c >> 5) << 4) | (c & 15);
        int slot = ((c >> 4) & 1) * 2;
        float v[4] = {pv[i].x, pv[i].y, pv[i].z, pv[i].w};
#pragma unroll
        for (int j = 0; j < 4; j++) {
            int d   = sc + j;
            int gsw = (g & 56) | ((g ^ (d >> 2)) & 7);
            float* p = &dst[d * 256 + gsw * 4 + slot];
            p[0] = v[j];
            p[1] = v[j];
        }
    }
}

// 16 k-steps (half a stage). A: 2 LDS.128 broadcast (token pairs packed);
// B: 4 LDS.128 (8 dup'd codes), conflict-free; 32 FFMA2 per k, zero MOVs.
__device__ __forceinline__ void compute_half(const float* __restrict__ Ab,
                                             const float* __restrict__ Bb,
                                             unsigned long long acc[4][8],
                                             int tx, int ty, int half) {
#pragma unroll 1
    for (int kg = 0; kg < 4; kg++) {
        int e    = half * 4 + kg;                       // = k>>2
        int aoff = (((2 * ty) & 24) | (((2 * ty) ^ e) & 7)) * 4;
        int boff = ((tx & 8) | ((tx ^ e) & 7)) * 4;
#pragma unroll
        for (int kk = 0; kk < 4; kk++) {
            int k = e * 4 + kk;
            const float* Ar = Ab + k * 128;
            const float* Br = Bb + k * 256;
            ulonglong2 A0 = *(const ulonglong2*)(Ar + aoff);
            ulonglong2 A1 = *(const ulonglong2*)(Ar + (aoff ^ 4));
            ulonglong2 B0 = *(const ulonglong2*)(Br + boff);
            ulonglong2 B1 = *(const ulonglong2*)(Br + boff + 64);
            ulonglong2 B2 = *(const ulonglong2*)(Br + boff + 128);
            ulonglong2 B3 = *(const ulonglong2*)(Br + boff + 192);
            unsigned long long ap[4] = {A0.x, A0.y, A1.x, A1.y};
            unsigned long long bp[8] = {B0.x, B0.y, B1.x, B1.y,
                                        B2.x, B2.y, B3.x, B3.y};
#pragma unroll
            for (int p = 0; p < 4; p++)
#pragma unroll
                for (int j = 0; j < 8; j++)
                    acc[p][j] = fma_f32x2(ap[p], bp[j], acc[p][j]);
        }
    }
}

__global__ __launch_bounds__(256, 2)
void gemm_argmin_kernel(const float* __restrict__ X,
                        const float* __restrict__ C) {
    extern __shared__ float sm[];
    float* As  = sm;            // [2][32][128]
    float* BsD = sm + SM_B;     // [2][32][256] duplicated
    float* cn  = sm + SM_CN;    // [256]
    float* xn  = sm + SM_XN;    // [128]

    const int tid  = threadIdx.x;
    const int tx   = tid & 15;
    const int ty   = tid >> 4;
    const int tile = (int)blockIdx.x >> 2;
    const int q    = (int)blockIdx.x & 3;
    const int bm   = tile * 128;
    const int kbase = q * 256;
    const int sr = tid >> 3;          // 0..31
    const int sc = (tid & 7) * 4;     // 0,4..28

    cn[tid] = g_cnorm[kbase + tid];
    if (tid < 128) xn[tid] = g_xnorm[bm + tid];

    const float* Xb = X + (size_t)bm * DIM;

    float4 pv[4];
    // prologue: stage s=0 (chunk 0, d-stage 0) into buffer 0
#pragma unroll
    for (int i = 0; i < 4; i++)
        pv[i] = *(const float4*)(Xb + (size_t)(sr + 32 * i) * DIM + sc);
    stage_A(As, pv, sr, sc);
#pragma unroll
    for (int i = 0; i < 4; i++)
        pv[i] = *(const float4*)(C + (size_t)(kbase + sr + 32 * i) * DIM + sc);
    stage_B(BsD, pv, sr, sc);
    __syncthreads();

    for (int cc = 0; cc < 2; cc++) {
        unsigned long long acc[4][8];
#pragma unroll
        for (int p = 0; p < 4; p++)
#pragma unroll
            for (int j = 0; j < 8; j++) acc[p][j] = 0ULL;

        for (int d0 = 0; d0 < 8; d0++) {
            int  s   = cc * 8 + d0;
            int  cur = s & 1;
            bool hn  = (s < 15);
            int  nd0 = (s + 1) & 7;
            int  ncc = (s + 1) >> 3;
            const float* Acur = As + cur * 4096;
            const float* Bcur = BsD + cur * 8192;
            float* Anxt = As + (cur ^ 1) * 4096;
            float* Bnxt = BsD + (cur ^ 1) * 8192;

            if (hn) {
#pragma unroll
                for (int i = 0; i < 4; i++)
                    pv[i] = *(const float4*)(Xb + (size_t)(sr + 32 * i) * DIM
                                             + nd0 * 32 + sc);
            }
            compute_half(Acur, Bcur, acc, tx, ty, 0);
            if (hn) {
                stage_A(Anxt, pv, sr, sc);
#pragma unroll
                for (int i = 0; i < 4; i++)
                    pv[i] = *(const float4*)(C
                            + (size_t)(kbase + ncc * 128 + sr + 32 * i) * DIM
                            + nd0 * 32 + sc);
            }
            compute_half(Acur, Bcur, acc, tx, ty, 1);
            if (hn) stage_B(Bnxt, pv, sr, sc);
            __syncthreads();
        }

        // reference-faithful epilogue for this chunk:
        //   dist = fp32(fp32(xn + cn) - 2*dot); per-thread codes ascend
        //   (cl = cc*128 + tx + 16j), strict < keeps lowest index; cross-lane
        //   reduce ties to lower index.
#pragma unroll
        for (int p = 0; p < 4; p++) {
#pragma unroll
            for (int h = 0; h < 2; h++) {
                int   t  = 8 * ty + 2 * p + h;
                float xv = xn[t];
                float bs = 3.4e38f;
                int   bi = 0;
#pragma unroll
                for (int j = 0; j < 8; j++) {
                    float2 d2 = unpack_f32x2(acc[p][j]);
                    float dot = h ? d2.y : d2.x;
                    int   cl  = cc * 128 + tx + 16 * j;
                    float sd  = (xv + cn[cl]) - 2.0f * dot;
                    if (sd < bs) { bs = sd; bi = cl; }
                }
#pragma unroll
                for (int off = 8; off >= 1; off >>= 1) {
                    float os = __shfl_xor_sync(0xffffffffu, bs, off);
                    int   oi = __shfl_xor_sync(0xffffffffu, bi, off);
                    if (os < bs || (os == bs && oi < bi)) { bs = os; bi = oi; }
                }
                if (tx == 0) {
                    int seg = q * 2 + cc;
                    g_hdist[seg * NTOK + bm + t] = bs;
                    g_hidx [seg * NTOK + bm + t] = kbase + bi;
                }
            }
        }
    }
}

// ---------------------------------------------------------------------------
// 3) merge 8 segments + gather/quantize + loss + EMA histogram. 1 warp/token.
//    segments are ascending code ranges; strict < keeps the lowest index.
// ---------------------------------------------------------------------------
__global__ void assign_kernel(const float* __restrict__ X,
                              const float* __restrict__ C,
                              float* __restrict__ outQ,
                              float* __restrict__ out_idx) {
    int n    = (blockIdx.x * blockDim.x + threadIdx.x) >> 5;
    int lane = threadIdx.x & 31;

    float bs = g_hdist[n];
    int   bi = g_hidx[n];
#pragma unroll
    for (int s = 1; s < 8; s++) {
        float v  = g_hdist[s * NTOK + n];
        int   iv = g_hidx[s * NTOK + n];
        if (v < bs) { bs = v; bi = iv; }
    }
    int idx = bi;
    if (lane == 0) out_idx[n] = (float)idx;

    const float4* xr = (const float4*)(X + (size_t)n * DIM);
    const float4* cr = (const float4*)(C + (size_t)idx * DIM);
    float4*       qr = (float4*)(outQ + (size_t)n * DIM);
    float* dwrow = &g_dw[(size_t)idx * DIM];

    float local = 0.0f;
#pragma unroll
    for (int h = 0; h < 2; h++) {
        int e = lane + h * 32;
        float4 xv = xr[e];
        float4 cv = cr[e];
        float4 qv;
        float d;
        d = cv.x - xv.x; qv.x = xv.x + d; local += d * d;
        d = cv.y - xv.y; qv.y = xv.y + d; local += d * d;
        d = cv.z - xv.z; qv.z = xv.z + d; local += d * d;
        d = cv.w - xv.w; qv.w = xv.w + d; local += d * d;
        qr[e] = qv;
        int db = e * 4;
        atomicAdd(&dwrow[db + 0], xv.x);
        atomicAdd(&dwrow[db + 1], xv.y);
        atomicAdd(&dwrow[db + 2], xv.z);
        atomicAdd(&dwrow[db + 3], xv.w);
    }
    if (lane == 0) atomicAdd(&g_counts[idx], 1.0f);

#pragma unroll
    for (int off = 16; off >= 1; off >>= 1)
        local += __shfl_xor_sync(0xffffffffu, local, off);
    if (lane == 0) atomicAdd(&g_loss, (double)local);
}

// ---------------------------------------------------------------------------
// 4) stats: new_cs (laplace-smoothed), perplexity, vq_loss. 1 block x 1024.
// ---------------------------------------------------------------------------
__global__ void stats_kernel(const float* __restrict__ ema_cs,
                             float* __restrict__ out_loss,
                             float* __restrict__ out_perp,
                             float* __restrict__ out_newcs) {
    __shared__ float sh[KCB];
    int k = threadIdx.x;

    float cnt = g_counts[k];
    float cs  = 0.99f * ema_cs[k] + 0.01f * cnt;

    sh[k] = cs;
    __syncthreads();
    for (int s = 512; s > 0; s >>= 1) {
        if (k < s) sh[k] += sh[k + s];
        __syncthreads();
    }
    float n_total = sh[0];
    __syncthreads();

    float ncs = (cs + 1e-5f) / (n_total + 0.01024f) * n_total;
    out_newcs[k] = ncs;
    g_newcs[k]   = ncs;

    float p = cnt * (1.0f / 65536.0f);
    sh[k] = p * logf(p + 1e-10f);
    __syncthreads();
    for (int s = 512; s > 0; s >>= 1) {
        if (k < s) sh[k] += sh[k + s];
        __syncthreads();
    }
    if (k == 0) {
        out_perp[0] = expf(-sh[0]);
        out_loss[0] = (float)(0.25 * g_loss / 16777216.0);
    }
}

// ---------------------------------------------------------------------------
// 5) new_ema_w, new_weight
// ---------------------------------------------------------------------------
__global__ void weights_kernel(const float* __restrict__ emaW,
                               float* __restrict__ outEmaW,
                               float* __restrict__ outW) {
    int i = blockIdx.x * blockDim.x + threadIdx.x;   // 0 .. K*D-1
    float w = 0.99f * emaW[i] + 0.01f * g_dw[i];
    outEmaW[i] = w;
    outW[i]    = w / g_newcs[i >> 8];
}

// ---------------------------------------------------------------------------
extern "C" void kernel_launch(void* const* d_in, const int* in_sizes, int n_in,
                              void* d_out, int out_size) {
    const float* X      = (const float*)d_in[0];   // inputs [N, D]
    const float* CB     = (const float*)d_in[1];   // codebook [K, D]
    const float* EMA_CS = (const float*)d_in[2];   // [K]
    const float* EMA_W  = (const float*)d_in[3];   // [K, D]
    float* out = (float*)d_out;

    float* out_q     = out;
    float* out_loss  = out + OFF_LOSS;
    float* out_idx   = out + OFF_IDX;
    float* out_perp  = out + OFF_PERP;
    float* out_ncs   = out + OFF_NCS;
    float* out_emaw  = out + OFF_EMAW;
    float* out_w     = out + OFF_W;

    float* g_cnorm_p;  cudaGetSymbolAddress((void**)&g_cnorm_p, g_cnorm);
    float* g_xnorm_p;  cudaGetSymbolAddress((void**)&g_xnorm_p, g_xnorm);

    cudaFuncSetAttribute(gemm_argmin_kernel,
                         cudaFuncAttributeMaxDynamicSharedMemorySize,
                         SMEM_BYTES);

    zero_kernel<<<256, 256>>>();
    rownorm_kernel<<<KCB * 32 / 256, 256>>>(CB, g_cnorm_p, KCB);
    rownorm_kernel<<<NTOK * 32 / 256, 256>>>(X, g_xnorm_p, NTOK);
    gemm_argmin_kernel<<<(NTOK / 128) * 4, 256, SMEM_BYTES>>>(X, CB);
    assign_kernel<<<NTOK / 8, 256>>>(X, CB, out_q, out_idx);
    stats_kernel<<<1, 1024>>>(EMA_CS, out_loss, out_perp, out_ncs);
    weights_kernel<<<KCB * DIM / 1024, 1024>>>(EMA_W, out_emaw, out_w);
}

// round 11
// speedup vs baseline: 1.2397x; 1.2397x over previous
#include <cuda_runtime.h>
#include <cuda_bf16.h>
#include <math.h>

// ---------------------------------------------------------------------------
// VQ-VAE vector quantizer, GB300 sm_103a
//   N=65536 tokens, D=256, K=1024 codes, fp32
//
// Reference-rounding-faithful distance:
//   dist_k = fp32( fp32(xnorm + cnorm_k) - 2*dot_k )
//   dot_k  = sequential fp32 FMA chain over d = 0..255 ascending
//   argmin = lowest index on exactly-equal rounded distances
//
// GEMM v5b: 512-thread CTA, 1 CTA/SM (4 warps/SMSP). Resident X^T tile
// (128 tok x 256 d, staged once, XOR-swizzled). B streamed: 256-code chunk
// x 32-d stages, double buffered, half-stage prefetch. A LDS are warp-
// uniform broadcasts (ty = warp id). Accumulators hold code pairs (FFMA2).
// Each (half, chunk) writes its reduced best to gmem as a segment; the 4
// ascending segments are merged in assign_kernel (strict <, lowest index).
// ---------------------------------------------------------------------------

#define NTOK 65536
#define DIM  256
#define KCB  1024

#define OFF_LOSS   16777216
#define OFF_IDX    16777217
#define OFF_PERP   16842753
#define OFF_NCS    16842754
#define OFF_EMAW   16843778
#define OFF_W      17105922

// scratch (device globals -- no allocation allowed)
__device__ float  g_cnorm[KCB];
__device__ float  g_xnorm[NTOK];
__device__ float  g_counts[KCB];
__device__ float  g_dw[KCB * DIM];
__device__ double g_loss;
__device__ float  g_newcs[KCB];
__device__ float  g_hdist[4 * NTOK];   // per-segment best rounded distance
__device__ int    g_hidx[4 * NTOK];    // per-segment best (global) index

// ---------------------------------------------------------------------------
// packed f32x2 helpers (Blackwell FFMA2 -- only reachable via PTX). Each lane
// is an independent IEEE RNE fp32 FMA -> bit-identical to scalar fmaf chains.
// ---------------------------------------------------------------------------
__device__ __forceinline__ unsigned long long dup_f32x2(float a) {
    unsigned long long r;
    asm("mov.b64 %0, {%1, %1};" : "=l"(r) : "f"(a));
    return r;
}
__device__ __forceinline__ unsigned long long fma_f32x2(unsigned long long a,
                                                        unsigned long long b,
                                                        unsigned long long c) {
    unsigned long long d;
    asm("fma.rn.f32x2 %0, %1, %2, %3;" : "=l"(d) : "l"(a), "l"(b), "l"(c));
    return d;
}
__device__ __forceinline__ float2 unpack_f32x2(unsigned long long v) {
    float2 r;
    asm("mov.b64 {%0, %1}, %2;" : "=f"(r.x), "=f"(r.y) : "l"(v));
    return r;
}

// ---------------------------------------------------------------------------
// 0) zero scratch
// ---------------------------------------------------------------------------
__global__ void zero_kernel() {
    int i = blockIdx.x * blockDim.x + threadIdx.x;
    int stride = gridDim.x * blockDim.x;
    for (int j = i; j < KCB * DIM; j += stride) g_dw[j] = 0.0f;
    if (i < KCB) g_counts[i] = 0.0f;
    if (i == 0)  g_loss = 0.0;
}

// ---------------------------------------------------------------------------
// 1) row squared-norms: one warp per row. (xnorm ulp jitter shifts a token's
//    whole distance row by the same lattice amount: order/tie preserving.)
// ---------------------------------------------------------------------------
__global__ void rownorm_kernel(const float* __restrict__ M,
                               float* __restrict__ out, int nrows) {
    int w    = (blockIdx.x * blockDim.x + threadIdx.x) >> 5;
    int lane = threadIdx.x & 31;
    if (w >= nrows) return;
    const float4* row = (const float4*)(M + (size_t)w * DIM);
    float s = 0.0f;
    float4 v = row[lane];
    s += v.x * v.x + v.y * v.y + v.z * v.z + v.w * v.w;
    v = row[32 + lane];
    s += v.x * v.x + v.y * v.y + v.z * v.z + v.w * v.w;
#pragma unroll
    for (int off = 16; off >= 1; off >>= 1)
        s += __shfl_xor_sync(0xffffffffu, s, off);
    if (lane == 0) out[w] = s;
}

// ---------------------------------------------------------------------------
// 2) fused GEMM + reference-rounded argmin
//    block = 128 tokens x 512 codes (half of K), 512 threads, tile 8x8.
//    smem: As[256][128] 128KB resident + Bs[2][32][256] 32KB + cn[512].
// ---------------------------------------------------------------------------
#define SM_BS 32768
#define SM_CN 49152
#define SMEM_BYTES (49664 * 4)

// 16 k-steps (one half stage). A loads: warp-uniform broadcast LDS.128.
// B loads: conflict-free permutation LDS.128. 32 FFMA2 + 8 dup MOV per k.
__device__ __forceinline__ void compute_half(const float* __restrict__ Ab,
                                             const float* __restrict__ Bb,
                                             unsigned long long acc[8][4],
                                             int tx, int ty, int h) {
#pragma unroll
    for (int kk4 = 0; kk4 < 4; kk4++) {
        const int kk   = h * 4 + kk4;   // = k>>2, XOR swizzle key
        const int aoff = ((ty & 8) | ((ty ^ kk) & 7)) * 4;
        const int boff = ((tx & 24) | ((tx ^ kk) & 7)) * 4;
#pragma unroll
        for (int m = 0; m < 4; m++) {
            const int k = kk * 4 + m;
            const float* Ar = Ab + k * 128;
            const float* Br = Bb + k * 256;
            float4 a0 = *(const float4*)(Ar + aoff);         // broadcast
            float4 a1 = *(const float4*)(Ar + 64 + aoff);    // broadcast
            ulonglong2 b0 = *(const ulonglong2*)(Br + boff);
            ulonglong2 b1 = *(const ulonglong2*)(Br + 128 + boff);
            float av[8] = {a0.x, a0.y, a0.z, a0.w, a1.x, a1.y, a1.z, a1.w};
            unsigned long long bv[4] = {b0.x, b0.y, b1.x, b1.y};
#pragma unroll
            for (int r = 0; r < 8; r++) {
                unsigned long long ad = dup_f32x2(av[r]);
#pragma unroll
                for (int j = 0; j < 4; j++)
                    acc[r][j] = fma_f32x2(ad, bv[j], acc[r][j]);
            }
        }
    }
}

// stage 2 float4 of the B tile (codes sb_c + 64*(i0..i0+1); d-cols sb_sc..+3)
__device__ __forceinline__ void stage_B2(float* __restrict__ dst,
                                         const float4* cv, int sb_c, int sb_sc,
                                         int i0) {
#pragma unroll
    for (int i = 0; i < 2; i++) {
        int c = sb_c + 64 * (i0 + i);
        int g = c >> 2;
        float v[4] = {cv[i].x, cv[i].y, cv[i].z, cv[i].w};
#pragma unroll
        for (int j = 0; j < 4; j++) {
            int d   = sb_sc + j;
            int gsw = (g & 56) | ((g ^ (d >> 2)) & 7);
            dst[d * 256 + gsw * 4 + (c & 3)] = v[j];
        }
    }
}

__global__ __launch_bounds__(512, 1)
void gemm_argmin_kernel(const float* __restrict__ X,
                        const float* __restrict__ C) {
    extern __shared__ float sm[];
    float* As = sm;             // [256][128] swizzled, resident
    float* Bs = sm + SM_BS;     // [2][32][256] swizzled
    float* cn = sm + SM_CN;     // [512]

    const int tid   = threadIdx.x;
    const int tx    = tid & 31;      // code group (0..31)
    const int ty    = tid >> 5;      // token group = warp id (0..15)
    const int tile  = (int)blockIdx.x >> 1;
    const int half  = (int)blockIdx.x & 1;
    const int bm    = tile * 128;
    const int kbase = half * 512;

    cn[tid] = g_cnorm[kbase + tid];

    // stage resident X^T tile once (swizzled [d][tok], row = 128 floats)
    {
        int tok = tid >> 2;
        int cb  = (tid & 3) * 4;
        int g   = tok >> 2;
        const float* xr = X + (size_t)(bm + tok) * DIM;
#pragma unroll
        for (int ii = 0; ii < 16; ii++) {
            float4 v = *(const float4*)(xr + cb + 16 * ii);
            float vv[4] = {v.x, v.y, v.z, v.w};
#pragma unroll
            for (int j = 0; j < 4; j++) {
                int d   = cb + 16 * ii + j;
                int gsw = (g & 24) | ((g ^ (d >> 2)) & 7);
                As[d * 128 + gsw * 4 + (tok & 3)] = vv[j];
            }
        }
    }

    const int sb_c  = tid >> 3;        // 0..63
    const int sb_sc = (tid & 7) * 4;   // 0,4..28

    // prologue: B chunk 0, d-stage 0 -> buffer 0
    float4 cv[2];
#pragma unroll
    for (int i = 0; i < 2; i++)
        cv[i] = *(const float4*)(C + (size_t)(kbase + sb_c + 64 * i) * DIM + sb_sc);
    stage_B2(Bs, cv, sb_c, sb_sc, 0);
#pragma unroll
    for (int i = 0; i < 2; i++)
        cv[i] = *(const float4*)(C + (size_t)(kbase + sb_c + 64 * (2 + i)) * DIM + sb_sc);
    stage_B2(Bs, cv, sb_c, sb_sc, 2);
    __syncthreads();

    float xnr[8];
#pragma unroll
    for (int r = 0; r < 8; r++) {
        int row = bm + ((r < 4) ? (ty * 4 + r) : (64 + ty * 4 + (r - 4)));
        xnr[r] = g_xnorm[row];
    }

    for (int cc = 0; cc < 2; cc++) {
        unsigned long long acc[8][4];
#pragma unroll
        for (int r = 0; r < 8; r++)
#pragma unroll
            for (int j = 0; j < 4; j++) acc[r][j] = 0ULL;

        for (int d0 = 0; d0 < 8; d0++) {
            int  s   = cc * 8 + d0;
            int  cur = s & 1;
            bool hn  = (s < 15);
            int  nd0 = (s + 1) & 7;
            int  ncc = (s + 1) >> 3;
            const float* Acur = As + d0 * 4096;    // A spans all 256 d
            const float* Bcur = Bs + cur * 8192;
            float* Bnxt = Bs + (cur ^ 1) * 8192;
            const float* Cnxt = C + (size_t)(kbase + ncc * 256 + sb_c) * DIM
                                  + nd0 * 32 + sb_sc;

            if (hn) {
#pragma unroll
                for (int i = 0; i < 2; i++)
                    cv[i] = *(const float4*)(Cnxt + (size_t)(64 * i) * DIM);
            }
            compute_half(Acur, Bcur, acc, tx, ty, 0);
            if (hn) {
                stage_B2(Bnxt, cv, sb_c, sb_sc, 0);
#pragma unroll
                for (int i = 0; i < 2; i++)
                    cv[i] = *(const float4*)(Cnxt + (size_t)(64 * (2 + i)) * DIM);
            }
            compute_half(Acur, Bcur, acc, tx, ty, 1);
            if (hn) stage_B2(Bnxt, cv, sb_c, sb_sc, 2);
            __syncthreads();
        }

        // reference-faithful epilogue: dist = fp32(fp32(xn + cn) - 2*dot),
        // codes scanned ascending (strict < keeps lowest index). Each
        // (half, chunk) segment goes straight to gmem; merged in assign.
#pragma unroll
        for (int r = 0; r < 8; r++) {
            float bs = 3.4e38f;
            int   bi = 0;
#pragma unroll
            for (int j = 0; j < 4; j++) {
                float2 v = unpack_f32x2(acc[r][j]);
                int cl = cc * 256 +
                         ((j < 2) ? (tx * 4 + 2 * j) : (128 + tx * 4 + 2 * (j - 2)));
                float s0 = (xnr[r] + cn[cl])     - 2.0f * v.x;
                float s1 = (xnr[r] + cn[cl + 1]) - 2.0f * v.y;
                if (s0 < bs) { bs = s0; bi = cl; }
                if (s1 < bs) { bs = s1; bi = cl + 1; }
            }
#pragma unroll
            for (int off = 16; off >= 1; off >>= 1) {
                float os = __shfl_xor_sync(0xffffffffu, bs, off);
                int   oi = __shfl_xor_sync(0xffffffffu, bi, off);
                if (os < bs || (os == bs && oi < bi)) { bs = os; bi = oi; }
            }
            if (tx == 0) {
                int seg = half * 2 + cc;
                int row = bm + ((r < 4) ? (ty * 4 + r) : (64 + ty * 4 + (r - 4)));
                g_hdist[seg * NTOK + row] = bs;
                g_hidx [seg * NTOK + row] = kbase + bi;
            }
        }
    }
}

// ---------------------------------------------------------------------------
// 3) merge 4 segments + gather/quantize + loss + EMA histogram. 1 warp/token.
//    segments are ascending code ranges; strict < keeps the lowest index.
// ---------------------------------------------------------------------------
__global__ void assign_kernel(const float* __restrict__ X,
                              const float* __restrict__ C,
                              float* __restrict__ outQ,
                              float* __restrict__ out_idx) {
    int n    = (blockIdx.x * blockDim.x + threadIdx.x) >> 5;
    int lane = threadIdx.x & 31;

    float bs = g_hdist[n];
    int   bi = g_hidx[n];
#pragma unroll
    for (int s = 1; s < 4; s++) {
        float v  = g_hdist[s * NTOK + n];
        int   iv = g_hidx[s * NTOK + n];
        if (v < bs) { bs = v; bi = iv; }
    }
    int idx = bi;
    if (lane == 0) out_idx[n] = (float)idx;

    const float4* xr = (const float4*)(X + (size_t)n * DIM);
    const float4* cr = (const float4*)(C + (size_t)idx * DIM);
    float4*       qr = (float4*)(outQ + (size_t)n * DIM);
    float* dwrow = &g_dw[(size_t)idx * DIM];

    float local = 0.0f;
#pragma unroll
    for (int h = 0; h < 2; h++) {
        int e = lane + h * 32;
        float4 xv = xr[e];
        float4 cv = cr[e];
        float4 qv;
        float d;
        d = cv.x - xv.x; qv.x = xv.x + d; local += d * d;
        d = cv.y - xv.y; qv.y = xv.y + d; local += d * d;
        d = cv.z - xv.z; qv.z = xv.z + d; local += d * d;
        d = cv.w - xv.w; qv.w = xv.w + d; local += d * d;
        qr[e] = qv;
        int db = e * 4;
        atomicAdd(&dwrow[db + 0], xv.x);
        atomicAdd(&dwrow[db + 1], xv.y);
        atomicAdd(&dwrow[db + 2], xv.z);
        atomicAdd(&dwrow[db + 3], xv.w);
    }
    if (lane == 0) atomicAdd(&g_counts[idx], 1.0f);

#pragma unroll
    for (int off = 16; off >= 1; off >>= 1)
        local += __shfl_xor_sync(0xffffffffu, local, off);
    if (lane == 0) atomicAdd(&g_loss, (double)local);
}

// ---------------------------------------------------------------------------
// 4) stats: new_cs (laplace-smoothed), perplexity, vq_loss. 1 block x 1024.
// ---------------------------------------------------------------------------
__global__ void stats_kernel(const float* __restrict__ ema_cs,
                             float* __restrict__ out_loss,
                             float* __restrict__ out_perp,
                             float* __restrict__ out_newcs) {
    __shared__ float sh[KCB];
    int k = threadIdx.x;

    float cnt = g_counts[k];
    float cs  = 0.99f * ema_cs[k] + 0.01f * cnt;

    sh[k] = cs;
    __syncthreads();
    for (int s = 512; s > 0; s >>= 1) {
        if (k < s) sh[k] += sh[k + s];
        __syncthreads();
    }
    float n_total = sh[0];
    __syncthreads();

    float ncs = (cs + 1e-5f) / (n_total + 0.01024f) * n_total;
    out_newcs[k] = ncs;
    g_newcs[k]   = ncs;

    float p = cnt * (1.0f / 65536.0f);
    sh[k] = p * logf(p + 1e-10f);
    __syncthreads();
    for (int s = 512; s > 0; s >>= 1) {
        if (k < s) sh[k] += sh[k + s];
        __syncthreads();
    }
    if (k == 0) {
        out_perp[0] = expf(-sh[0]);
        out_loss[0] = (float)(0.25 * g_loss / 16777216.0);
    }
}

// ---------------------------------------------------------------------------
// 5) new_ema_w, new_weight
// ---------------------------------------------------------------------------
__global__ void weights_kernel(const float* __restrict__ emaW,
                               float* __restrict__ outEmaW,
                               float* __restrict__ outW) {
    int i = blockIdx.x * blockDim.x + threadIdx.x;   // 0 .. K*D-1
    float w = 0.99f * emaW[i] + 0.01f * g_dw[i];
    outEmaW[i] = w;
    outW[i]    = w / g_newcs[i >> 8];
}

// ---------------------------------------------------------------------------
extern "C" void kernel_launch(void* const* d_in, const int* in_sizes, int n_in,
                              void* d_out, int out_size) {
    const float* X      = (const float*)d_in[0];   // inputs [N, D]
    const float* CB     = (const float*)d_in[1];   // codebook [K, D]
    const float* EMA_CS = (const float*)d_in[2];   // [K]
    const float* EMA_W  = (const float*)d_in[3];   // [K, D]
    float* out = (float*)d_out;

    float* out_q     = out;
    float* out_loss  = out + OFF_LOSS;
    float* out_idx   = out + OFF_IDX;
    float* out_perp  = out + OFF_PERP;
    float* out_ncs   = out + OFF_NCS;
    float* out_emaw  = out + OFF_EMAW;
    float* out_w     = out + OFF_W;

    float* g_cnorm_p;  cudaGetSymbolAddress((void**)&g_cnorm_p, g_cnorm);
    float* g_xnorm_p;  cudaGetSymbolAddress((void**)&g_xnorm_p, g_xnorm);

    cudaFuncSetAttribute(gemm_argmin_kernel,
                         cudaFuncAttributeMaxDynamicSharedMemorySize,
                         SMEM_BYTES);

    zero_kernel<<<256, 256>>>();
    rownorm_kernel<<<KCB * 32 / 256, 256>>>(CB, g_cnorm_p, KCB);
    rownorm_kernel<<<NTOK * 32 / 256, 256>>>(X, g_xnorm_p, NTOK);
    gemm_argmin_kernel<<<(NTOK / 128) * 2, 512, SMEM_BYTES>>>(X, CB);
    assign_kernel<<<NTOK / 8, 256>>>(X, CB, out_q, out_idx);
    stats_kernel<<<1, 1024>>>(EMA_CS, out_loss, out_perp, out_ncs);
    weights_kernel<<<KCB * DIM / 1024, 1024>>>(EMA_W, out_emaw, out_w);
}